// round 8
// baseline (speedup 1.0000x reference)
#include <cuda_runtime.h>
#include <cuda_bf16.h>
#include <cstdint>
#include <cstddef>

#define BT   2048
#define Hh   1280
#define Ee   896
#define NEXP 64
#define TOPK 6
#define FFN  1792
#define TOT  (BT*TOPK)

// ---------------- device scratch ----------------
// int8 hi/lo weights, repacked per-expert row-major [n-row][k]
__device__ int8_t qWg_h[(size_t)NEXP*Ee*Hh], qWg_l[(size_t)NEXP*Ee*Hh];
__device__ int8_t qWu_h[(size_t)NEXP*Ee*Hh], qWu_l[(size_t)NEXP*Ee*Hh];
__device__ int8_t qWd_h[(size_t)NEXP*Hh*Ee], qWd_l[(size_t)NEXP*Hh*Ee];
__device__ int8_t qSg_h[(size_t)FFN*Hh], qSg_l[(size_t)FFN*Hh];
__device__ int8_t qSu_h[(size_t)FFN*Hh], qSu_l[(size_t)FFN*Hh];
__device__ int8_t qSd_h[(size_t)Hh*FFN], qSd_l[(size_t)Hh*FFN];
// int8 activations
__device__ int8_t qX_h[(size_t)BT*Hh],   qX_l[(size_t)BT*Hh];
__device__ int8_t qSh_h[(size_t)BT*FFN], qSh_l[(size_t)BT*FFN];
__device__ int8_t qA_h[(size_t)TOT*Ee],  qA_l[(size_t)TOT*Ee];
// scales (s = max/127)
__device__ float sX[BT];
__device__ float sSh[BT];
__device__ float sAct[TOT];
__device__ float sG[(size_t)NEXP*Ee];   // [n][e]
__device__ float sU[(size_t)NEXP*Ee];
__device__ float sD[(size_t)NEXP*Hh];   // [n][h]
__device__ float sSg[FFN], sSu[FFN], sSd[Hh];
// fp32 intermediates
__device__ float g_shf[(size_t)BT*FFN];    // shared silu(g)*u
__device__ float g_actf[(size_t)TOT*Ee];   // routed silu(g)*u
__device__ float g_dout[(size_t)TOT*Hh];   // per-slot weighted down out
// router
__device__ float g_logits[BT*NEXP];
__device__ int   g_topi[TOT];
__device__ float g_topw[TOT];
__device__ int   g_cnt[NEXP];
__device__ int   g_off[NEXP];
__device__ int   g_list[TOT];
__device__ float g_lw[TOT];
__device__ int   g_pos[TOT];

// ---------------- small kernels ----------------
__global__ void zero_cnt() { if (threadIdx.x < NEXP) g_cnt[threadIdx.x] = 0; }

__global__ void scan_off() {
    if (threadIdx.x == 0) {
        int a = 0;
        for (int n = 0; n < NEXP; n++) { g_off[n] = a; a += g_cnt[n]; }
    }
}

__global__ void router_topk() {
    int t = blockIdx.x;
    int lane = threadIdx.x;
    const float NEG = __int_as_float(0xff800000);
    float v0 = g_logits[t*NEXP + lane];
    float v1 = g_logits[t*NEXP + 32 + lane];
    int i0 = lane, i1 = lane + 32;
    float bv[TOPK]; int bi[TOPK];
    for (int k = 0; k < TOPK; k++) {
        float mv; int mi;
        if (v0 > v1 || (v0 == v1 && i0 < i1)) { mv = v0; mi = i0; } else { mv = v1; mi = i1; }
        for (int o = 16; o > 0; o >>= 1) {
            float ov = __shfl_xor_sync(0xffffffffu, mv, o);
            int   oi = __shfl_xor_sync(0xffffffffu, mi, o);
            if (ov > mv || (ov == mv && oi < mi)) { mv = ov; mi = oi; }
        }
        bv[k] = mv; bi[k] = mi;
        if (i0 == mi) v0 = NEG;
        if (i1 == mi) v1 = NEG;
    }
    float mx = bv[0];
    float s = 0.f, ev[TOPK];
    #pragma unroll
    for (int k = 0; k < TOPK; k++) { ev[k] = __expf(bv[k] - mx); s += ev[k]; }
    if (lane < TOPK) {
        g_topi[t*TOPK + lane] = bi[lane];
        g_topw[t*TOPK + lane] = ev[lane] / s;
        atomicAdd(&g_cnt[bi[lane]], 1);
    }
}

__global__ void build_lists() {
    int e = blockIdx.x;
    int tid = threadIdx.x;
    int lane = tid & 31, wid = tid >> 5;
    __shared__ int wcnt[8], wpre[8], stot;
    int base = g_off[e];
    int run = 0;
    for (int s0 = 0; s0 < TOT; s0 += 256) {
        int s = s0 + tid;
        bool p = (s < TOT) && (g_topi[s] == e);
        unsigned b = __ballot_sync(0xffffffffu, p);
        int wp = __popc(b & ((1u << lane) - 1u));
        if (lane == 0) wcnt[wid] = __popc(b);
        __syncthreads();
        if (tid == 0) {
            int a = 0;
            for (int w = 0; w < 8; w++) { wpre[w] = a; a += wcnt[w]; }
            stot = a;
        }
        __syncthreads();
        if (p) {
            int pos = base + run + wpre[wid] + wp;
            g_list[pos] = s / TOPK;
            g_lw[pos]   = g_topw[s];
            g_pos[s]    = pos;
        }
        run += stot;
        __syncthreads();
    }
}

// ---------------- quantization helpers ----------------
__device__ __forceinline__ void quant2(float v, float s, float inv, int8_t& h, int8_t& l) {
    float qh = rintf(v * inv);
    qh = fminf(fmaxf(qh, -127.f), 127.f);
    float r = v - qh * s;
    float ql = rintf(r * inv * 256.f);
    ql = fminf(fmaxf(ql, -127.f), 127.f);
    h = (int8_t)(int)qh; l = (int8_t)(int)ql;
}

// per-row quantize: grid = R blocks, 256 threads. C % 4 == 0.
__global__ void quant_rows(const float* __restrict__ src, int C,
                           int8_t* __restrict__ qh, int8_t* __restrict__ ql,
                           float* __restrict__ srow) {
    int r = blockIdx.x;
    const float4* p4 = (const float4*)(src + (size_t)r*C);
    int n4 = C >> 2;
    float m = 0.f;
    for (int i = threadIdx.x; i < n4; i += 256) {
        float4 v = p4[i];
        m = fmaxf(m, fmaxf(fmaxf(fabsf(v.x),fabsf(v.y)), fmaxf(fabsf(v.z),fabsf(v.w))));
    }
    __shared__ float red[8];
    __shared__ float sfin;
    for (int o = 16; o > 0; o >>= 1) m = fmaxf(m, __shfl_xor_sync(0xffffffffu, m, o));
    if ((threadIdx.x & 31) == 0) red[threadIdx.x >> 5] = m;
    __syncthreads();
    if (threadIdx.x == 0) {
        float t = red[0];
        #pragma unroll
        for (int i = 1; i < 8; i++) t = fmaxf(t, red[i]);
        float s = fmaxf(t, 1e-30f) * (1.f/127.f);
        sfin = s;
        srow[r] = s;
    }
    __syncthreads();
    float s = sfin, inv = 1.f / s;
    char4* h4p = (char4*)(qh + (size_t)r*C);
    char4* l4p = (char4*)(ql + (size_t)r*C);
    for (int i = threadIdx.x; i < n4; i += 256) {
        float4 v = p4[i];
        char4 h4, l4;
        int8_t a,b;
        quant2(v.x, s, inv, a, b); h4.x=a; l4.x=b;
        quant2(v.y, s, inv, a, b); h4.y=a; l4.y=b;
        quant2(v.z, s, inv, a, b); h4.z=a; l4.z=b;
        quant2(v.w, s, inv, a, b); h4.w=a; l4.w=b;
        h4p[i] = h4; l4p[i] = l4;
    }
}

// ---------------- weight max prepass ----------------
// gate/up: src [H][E][N]; out scale per (expert n, e): s[n*Ee + e]
__global__ void wmax_gu(const float* __restrict__ src, float* __restrict__ out) {
    int e = blockIdx.y;
    int n0 = blockIdx.x * 32;
    int tx = threadIdx.x, ty = threadIdx.y;
    float m = 0.f;
    for (int h = ty; h < Hh; h += 32)
        m = fmaxf(m, fabsf(src[(size_t)h*Ee*NEXP + (size_t)e*NEXP + n0 + tx]));
    __shared__ float sm_[32][33];
    sm_[ty][tx] = m;
    __syncthreads();
    for (int s = 16; s > 0; s >>= 1) {
        if (ty < s) sm_[ty][tx] = fmaxf(sm_[ty][tx], sm_[ty+s][tx]);
        __syncthreads();
    }
    if (ty == 0) out[(size_t)(n0+tx)*Ee + e] = fmaxf(sm_[0][tx], 1e-30f) * (1.f/127.f);
}

// down: src [E][H][N]; out scale per (expert n, h): s[n*Hh + h]
__global__ void wmax_dn(const float* __restrict__ src, float* __restrict__ out) {
    int h = blockIdx.y;
    int n0 = blockIdx.x * 32;
    int tx = threadIdx.x, ty = threadIdx.y;
    float m = 0.f;
    for (int e = ty; e < Ee; e += 32)
        m = fmaxf(m, fabsf(src[(size_t)e*Hh*NEXP + (size_t)h*NEXP + n0 + tx]));
    __shared__ float sm_[32][33];
    sm_[ty][tx] = m;
    __syncthreads();
    for (int s = 16; s > 0; s >>= 1) {
        if (ty < s) sm_[ty][tx] = fmaxf(sm_[ty][tx], sm_[ty+s][tx]);
        __syncthreads();
    }
    if (ty == 0) out[(size_t)(n0+tx)*Hh + h] = fmaxf(sm_[0][tx], 1e-30f) * (1.f/127.f);
}

// ---------------- repack + quantize ----------------
// gate/up: src [H][E][N] -> dst [n][e][h] int8 hi/lo; scale sRow[n*Ee + e]
__global__ void repackq_gu(const float* __restrict__ src, const float* __restrict__ sRow,
                           int8_t* __restrict__ dh, int8_t* __restrict__ dl) {
    __shared__ float s[32][33];
    int e = blockIdx.z;
    int h0 = blockIdx.x * 32, n0 = blockIdx.y * 32;
    int tx = threadIdx.x, ty = threadIdx.y;
    s[ty][tx] = src[(size_t)(h0+ty)*Ee*NEXP + (size_t)e*NEXP + (n0+tx)];
    __syncthreads();
    float v = s[tx][ty];   // (h = h0+tx, n = n0+ty)
    float sc = sRow[(size_t)(n0+ty)*Ee + e];
    int8_t h, l;
    quant2(v, sc, 1.f/sc, h, l);
    size_t o = (size_t)(n0+ty)*Ee*Hh + (size_t)e*Hh + (h0+tx);
    dh[o] = h; dl[o] = l;
}

// down: src [E][H][N] -> dst [n][h][e] int8 hi/lo; scale sRow[n*Hh + h]
__global__ void repackq_dn(const float* __restrict__ src, const float* __restrict__ sRow,
                           int8_t* __restrict__ dh, int8_t* __restrict__ dl) {
    __shared__ float s[32][33];
    int h = blockIdx.z;
    int e0 = blockIdx.x * 32, n0 = blockIdx.y * 32;
    int tx = threadIdx.x, ty = threadIdx.y;
    s[ty][tx] = src[(size_t)(e0+ty)*Hh*NEXP + (size_t)h*NEXP + (n0+tx)];
    __syncthreads();
    float v = s[tx][ty];   // (e = e0+tx, n = n0+ty)
    float sc = sRow[(size_t)(n0+ty)*Hh + h];
    int8_t hh, ll;
    quant2(v, sc, 1.f/sc, hh, ll);
    size_t o = (size_t)(n0+ty)*Hh*Ee + (size_t)h*Ee + (e0+tx);
    dh[o] = hh; dl[o] = ll;
}

// ---------------- fp32 router GEMM ----------------
__global__ __launch_bounds__(256) void router_gemm(
    const float* __restrict__ A, const float* __restrict__ B, float* __restrict__ C)
{
    const int m0 = blockIdx.x * 64;
    __shared__ __align__(16) float As[16][68];
    __shared__ __align__(16) float Bs[16][68];
    const int tid = threadIdx.x;
    const int tx = tid & 15, ty = tid >> 4;
    float acc[4][4];
    #pragma unroll
    for (int i = 0; i < 4; i++) for (int j = 0; j < 4; j++) acc[i][j] = 0.f;
    const int aCol = tid & 15, aRow0 = tid >> 4;
    for (int k0 = 0; k0 < Hh; k0 += 16) {
        #pragma unroll
        for (int i = 0; i < 4; i++)
            As[aCol][aRow0 + 16*i] = A[(size_t)(m0 + aRow0 + 16*i)*Hh + k0 + aCol];
        const int bK = tid & 15, bN0 = tid >> 4;
        #pragma unroll
        for (int i = 0; i < 4; i++)
            Bs[bK][bN0 + 16*i] = B[(size_t)(bN0 + 16*i)*Hh + k0 + bK];
        __syncthreads();
        #pragma unroll
        for (int kk = 0; kk < 16; kk++) {
            float4 a4 = *(const float4*)&As[kk][ty*4];
            float4 b4 = *(const float4*)&Bs[kk][tx*4];
            float av[4] = {a4.x,a4.y,a4.z,a4.w};
            float bv[4] = {b4.x,b4.y,b4.z,b4.w};
            #pragma unroll
            for (int i = 0; i < 4; i++) for (int j = 0; j < 4; j++) acc[i][j] += av[i]*bv[j];
        }
        __syncthreads();
    }
    #pragma unroll
    for (int i = 0; i < 4; i++) for (int j = 0; j < 4; j++)
        C[(size_t)(m0 + ty*4 + i)*NEXP + tx*4 + j] = acc[i][j];
}

// ---------------- IMMA / cp.async helpers ----------------
__device__ __forceinline__ void ldsm_x4(uint32_t* r, const void* p) {
    uint32_t a = (uint32_t)__cvta_generic_to_shared(p);
    asm volatile("ldmatrix.sync.aligned.m8n8.x4.shared.b16 {%0,%1,%2,%3}, [%4];"
        : "=r"(r[0]), "=r"(r[1]), "=r"(r[2]), "=r"(r[3]) : "r"(a));
}
__device__ __forceinline__ void imma16832(int* d, const uint32_t* a, const uint32_t* b) {
    asm volatile("mma.sync.aligned.m16n8k32.row.col.s32.s8.s8.s32 "
        "{%0,%1,%2,%3}, {%4,%5,%6,%7}, {%8,%9}, {%0,%1,%2,%3};"
        : "+r"(d[0]), "+r"(d[1]), "+r"(d[2]), "+r"(d[3])
        : "r"(a[0]), "r"(a[1]), "r"(a[2]), "r"(a[3]), "r"(b[0]), "r"(b[1]));
}
__device__ __forceinline__ void cp16(uint32_t dst, const void* src, bool pred) {
    int sz = pred ? 16 : 0;
    asm volatile("cp.async.ca.shared.global [%0], [%1], 16, %2;"
        :: "r"(dst), "l"(src), "r"(sz));
}
__device__ __forceinline__ void cp_commit() { asm volatile("cp.async.commit_group;" ::: "memory"); }
template<int N> __device__ __forceinline__ void cp_wait() { asm volatile("cp.async.wait_group %0;" :: "n"(N) : "memory"); }

// ---------------- split-int8 IMMA GEMM ----------------
// CTA 128 x CTA_N, K-tile 64, 3-stage cp.async ring. 8 warps.
// A: int8 hi/lo [rows][K]. B: int8 hi/lo per-expert [n][K]. Dequant: sa*sb*(hh + cross/256).
// MODE: 0 = fp32 store (plain rows), 1 = dual-B silu(g)*u fp32 store, 2 = weighted slot fp32 store
// AMODE: 0 = plain rows, 1 = gather via g_list (C rows = slots), 2 = rows are slots
template<int MODE, int AMODE>
__global__ __launch_bounds__(256) void imma_gemm(
    const int8_t* __restrict__ Ah, const int8_t* __restrict__ Al,
    const float* __restrict__ sA, int lda,
    const int8_t* __restrict__ B0h, const int8_t* __restrict__ B0l,
    const int8_t* __restrict__ B1h, const int8_t* __restrict__ B1l,
    const float* __restrict__ sB0, const float* __restrict__ sB1, int sbStride,
    size_t bStride,
    float* __restrict__ C, int ldc, int M, int K, int ntiles)
{
    constexpr int NB    = (MODE == 1) ? 4 : 2;
    constexpr int CTA_N = (MODE == 1) ? 32 : 64;
    constexpr int FN    = (MODE == 1) ? 2 : 4;
    constexpr int SZ_A  = 128*80;            // one A array per stage
    constexpr int SZ_B  = CTA_N*80;          // one B array per stage
    constexpr int OFF_B = 2*SZ_A;
    constexpr int STG   = 2*SZ_A + NB*SZ_B;  // 30720 both modes
    extern __shared__ __align__(16) char sm[];

    const int mt = blockIdx.x;
    int e, nt;
    if (AMODE != 0) { e = blockIdx.y / ntiles; nt = blockIdx.y % ntiles; }
    else            { e = 0;                   nt = blockIdx.y; }
    const int m0 = mt * 128, n0 = nt * CTA_N;
    int rows, base = 0;
    if (AMODE != 0) { rows = g_cnt[e]; base = g_off[e]; if (m0 >= rows) return; }
    else rows = M;

    const int8_t* bsrc[NB];
    bsrc[0] = B0h + (size_t)e * bStride;
    bsrc[1] = B0l + (size_t)e * bStride;
    if (MODE == 1) { bsrc[2] = B1h + (size_t)e * bStride; bsrc[3] = B1l + (size_t)e * bStride; }
    const float* sB0e = sB0 + (size_t)e * sbStride;
    const float* sB1e = (MODE == 1) ? (sB1 + (size_t)e * sbStride) : nullptr;

    const int tid = threadIdx.x, lane = tid & 31, wid = tid >> 5;
    const int wr = wid >> 1, wc = wid & 1;   // 4x2 warp grid

    const uint32_t smbase = (uint32_t)__cvta_generic_to_shared(sm);

    // A cp.async: 2 arrays x 128 rows x 4 chunks(16B) = 1024 -> 4/thread
    const int8_t* aSrc[4]; uint32_t aDst[4]; bool aOk[4];
    #pragma unroll
    for (int i = 0; i < 4; i++) {
        int idx = i*256 + tid;
        int a = idx >> 9, rem = idx & 511;
        int r = rem >> 2, q = rem & 3;
        int gm = m0 + r;
        bool ok = gm < rows;
        int row = 0;
        if (ok) {
            if (AMODE == 1)      row = g_list[base + gm];
            else if (AMODE == 2) row = base + gm;
            else                 row = gm;
        }
        aSrc[i] = (a ? Al : Ah) + (size_t)row * lda + q*16;
        aOk[i]  = ok;
        aDst[i] = (uint32_t)(a*SZ_A + r*80 + q*16);
    }
    // B cp.async: NB arrays x CTA_N rows x 4 chunks = 512 -> 2/thread
    const int8_t* bSrc[2]; uint32_t bDst[2];
    #pragma unroll
    for (int i = 0; i < 2; i++) {
        int idx = i*256 + tid;
        int arr = idx / (CTA_N*4), rem = idx % (CTA_N*4);
        int r = rem >> 2, q = rem & 3;
        bSrc[i] = bsrc[arr] + (size_t)(n0 + r) * K + q*16;
        bDst[i] = (uint32_t)(OFF_B + arr*SZ_B + r*80 + q*16);
    }

    int hhg[2][FN][4], xg[2][FN][4];
    int hhu[MODE == 1 ? 2 : 1][FN][4], xu[MODE == 1 ? 2 : 1][FN][4];
    #pragma unroll
    for (int fm = 0; fm < 2; fm++)
        #pragma unroll
        for (int fn = 0; fn < FN; fn++)
            #pragma unroll
            for (int q = 0; q < 4; q++) {
                hhg[fm][fn][q] = 0; xg[fm][fn][q] = 0;
                if (MODE == 1) { hhu[fm][fn][q] = 0; xu[fm][fn][q] = 0; }
            }

    const int nk = K / 64;

    // prologue: stages 0,1
    #pragma unroll
    for (int s = 0; s < 2; s++) {
        const uint32_t sb = smbase + (uint32_t)(s * STG);
        const int k0 = s * 64;
        #pragma unroll
        for (int i = 0; i < 4; i++) cp16(sb + aDst[i], aSrc[i] + k0, aOk[i]);
        #pragma unroll
        for (int i = 0; i < 2; i++) cp16(sb + bDst[i], bSrc[i] + k0, true);
        cp_commit();
    }

    for (int kt = 0; kt < nk; kt++) {
        const int st = kt % 3;
        if (kt + 2 < nk) {
            const int k0 = (kt + 2) * 64;
            const uint32_t sb = smbase + (uint32_t)(((kt + 2) % 3) * STG);
            #pragma unroll
            for (int i = 0; i < 4; i++) cp16(sb + aDst[i], aSrc[i] + k0, aOk[i]);
            #pragma unroll
            for (int i = 0; i < 2; i++) cp16(sb + bDst[i], bSrc[i] + k0, true);
            cp_commit();
            cp_wait<2>();
        } else if (kt + 1 < nk) {
            cp_wait<1>();
        } else {
            cp_wait<0>();
        }
        __syncthreads();

        char* pA = sm + st * STG;
        char* pB = pA + OFF_B;

        #pragma unroll
        for (int kc = 0; kc < 2; kc++) {
            // A fragments: [array h/l][fm]
            uint32_t fa[2][2][4];
            #pragma unroll
            for (int a = 0; a < 2; a++)
                #pragma unroll
                for (int fm = 0; fm < 2; fm++) {
                    int arow = wr*32 + fm*16 + (lane & 7) + ((lane >> 3) & 1)*8;
                    ldsm_x4(fa[a][fm], pA + a*SZ_A + arow*80 + kc*32 + ((lane >> 4)*16));
                }
            // B fragments: [array][fn][2]
            uint32_t fb[NB][FN][2];
            #pragma unroll
            for (int arr = 0; arr < NB; arr++)
                #pragma unroll
                for (int fp = 0; fp < FN/2; fp++) {
                    int brow = wc*(FN*8) + fp*16 + (lane & 7) + ((lane >> 3) & 1)*8;
                    uint32_t r4[4];
                    ldsm_x4(r4, pB + arr*SZ_B + brow*80 + kc*32 + ((lane >> 4)*16));
                    fb[arr][2*fp+0][0] = r4[0]; fb[arr][2*fp+1][0] = r4[1];
                    fb[arr][2*fp+0][1] = r4[2]; fb[arr][2*fp+1][1] = r4[3];
                }
            // IMMA
            #pragma unroll
            for (int fn = 0; fn < FN; fn++)
                #pragma unroll
                for (int fm = 0; fm < 2; fm++) {
                    imma16832(hhg[fm][fn], fa[0][fm], fb[0][fn]);
                    imma16832(xg [fm][fn], fa[0][fm], fb[1][fn]);
                    imma16832(xg [fm][fn], fa[1][fm], fb[0][fn]);
                    if (MODE == 1) {
                        imma16832(hhu[fm][fn], fa[0][fm], fb[2][fn]);
                        imma16832(xu [fm][fn], fa[0][fm], fb[3][fn]);
                        imma16832(xu [fm][fn], fa[1][fm], fb[2][fn]);
                    }
                }
        }
        __syncthreads();
    }

    // ---- epilogue ----
    const float INV256 = 1.f/256.f;
    #pragma unroll
    for (int fm = 0; fm < 2; fm++) {
        #pragma unroll
        for (int half = 0; half < 2; half++) {
            int gm = m0 + wr*32 + fm*16 + (lane >> 2) + half*8;
            if (AMODE != 0 && gm >= rows) continue;
            float sa; int crow;
            if (AMODE == 1)      { int tok = g_list[base + gm]; sa = sA[tok]; crow = base + gm; }
            else if (AMODE == 2) { crow = base + gm; sa = sA[crow]; }
            else                 { crow = gm; sa = sA[gm]; }
            float w = (MODE == 2) ? g_lw[base + gm] : 0.f;
            #pragma unroll
            for (int fn = 0; fn < FN; fn++) {
                int col = n0 + wc*(FN*8) + fn*8 + (lane & 3)*2;
                int i0 = half*2, i1 = half*2 + 1;
                float f0 = ((float)hhg[fm][fn][i0] + (float)xg[fm][fn][i0]*INV256) * sa * sB0e[col];
                float f1 = ((float)hhg[fm][fn][i1] + (float)xg[fm][fn][i1]*INV256) * sa * sB0e[col+1];
                if (MODE == 1) {
                    float u0 = ((float)hhu[fm][fn][i0] + (float)xu[fm][fn][i0]*INV256) * sa * sB1e[col];
                    float u1 = ((float)hhu[fm][fn][i1] + (float)xu[fm][fn][i1]*INV256) * sa * sB1e[col+1];
                    float a0 = f0 / (1.f + __expf(-f0)) * u0;
                    float a1 = f1 / (1.f + __expf(-f1)) * u1;
                    *(float2*)&C[(size_t)crow * ldc + col] = make_float2(a0, a1);
                } else if (MODE == 0) {
                    *(float2*)&C[(size_t)crow * ldc + col] = make_float2(f0, f1);
                } else {
                    *(float2*)&C[(size_t)crow * ldc + col] = make_float2(f0 * w, f1 * w);
                }
            }
        }
    }
}

// ---------------- final gather-reduce ----------------
__global__ void reduce_out(float* __restrict__ out) {
    int t = blockIdx.x;
    int p[TOPK];
    #pragma unroll
    for (int k = 0; k < TOPK; k++) p[k] = g_pos[t*TOPK + k];
    float4* o4 = (float4*)(out + (size_t)t * Hh);
    for (int c = threadIdx.x; c < Hh/4; c += blockDim.x) {
        float4 v = o4[c];
        #pragma unroll
        for (int k = 0; k < TOPK; k++) {
            float4 d = ((const float4*)(g_dout + (size_t)p[k] * Hh))[c];
            v.x += d.x; v.y += d.y; v.z += d.z; v.w += d.w;
        }
        o4[c] = v;
    }
}

// ---------------- launch ----------------
extern "C" void kernel_launch(void* const* d_in, const int* in_sizes, int n_in,
                              void* d_out, int out_size) {
    const float* x      = (const float*)d_in[0];
    const float* wr     = (const float*)d_in[1];
    const float* wgexp  = (const float*)d_in[2];
    const float* wuexp  = (const float*)d_in[3];
    const float* wdexp  = (const float*)d_in[4];
    const float* wsg    = (const float*)d_in[5];
    const float* wsu    = (const float*)d_in[6];
    const float* wsd    = (const float*)d_in[7];
    float* out = (float*)d_out;

    float *pLog, *pDout, *pShf, *pActf;
    float *psX,*psSh,*psAct,*psG,*psU,*psD,*psSg,*psSu,*psSd;
    int8_t *pWg_h,*pWg_l,*pWu_h,*pWu_l,*pWd_h,*pWd_l;
    int8_t *pSg_h,*pSg_l,*pSu_h,*pSu_l,*pSd_h,*pSd_l;
    int8_t *pX_h,*pX_l,*pSh_h,*pSh_l,*pA_h,*pA_l;
    cudaGetSymbolAddress((void**)&pLog, g_logits);
    cudaGetSymbolAddress((void**)&pDout, g_dout);
    cudaGetSymbolAddress((void**)&pShf, g_shf);
    cudaGetSymbolAddress((void**)&pActf, g_actf);
    cudaGetSymbolAddress((void**)&pWg_h, qWg_h); cudaGetSymbolAddress((void**)&pWg_l, qWg_l);
    cudaGetSymbolAddress((void**)&pWu_h, qWu_h); cudaGetSymbolAddress((void**)&pWu_l, qWu_l);
    cudaGetSymbolAddress((void**)&pWd_h, qWd_h); cudaGetSymbolAddress((void**)&pWd_l, qWd_l);
    cudaGetSymbolAddress((void**)&pSg_h, qSg_h); cudaGetSymbolAddress((void**)&pSg_l, qSg_l);
    cudaGetSymbolAddress((void**)&pSu_h, qSu_h); cudaGetSymbolAddress((void**)&pSu_l, qSu_l);
    cudaGetSymbolAddress((void**)&pSd_h, qSd_h); cudaGetSymbolAddress((void**)&pSd_l, qSd_l);
    cudaGetSymbolAddress((void**)&pX_h, qX_h);   cudaGetSymbolAddress((void**)&pX_l, qX_l);
    cudaGetSymbolAddress((void**)&pSh_h, qSh_h); cudaGetSymbolAddress((void**)&pSh_l, qSh_l);
    cudaGetSymbolAddress((void**)&pA_h, qA_h);   cudaGetSymbolAddress((void**)&pA_l, qA_l);
    cudaGetSymbolAddress((void**)&psX, sX);   cudaGetSymbolAddress((void**)&psSh, sSh);
    cudaGetSymbolAddress((void**)&psAct, sAct);
    cudaGetSymbolAddress((void**)&psG, sG);   cudaGetSymbolAddress((void**)&psU, sU);
    cudaGetSymbolAddress((void**)&psD, sD);
    cudaGetSymbolAddress((void**)&psSg, sSg); cudaGetSymbolAddress((void**)&psSu, sSu);
    cudaGetSymbolAddress((void**)&psSd, sSd);

    const int SM = 3 * 30720;   // 92160 B, all modes
    cudaFuncSetAttribute(imma_gemm<1,0>, cudaFuncAttributeMaxDynamicSharedMemorySize, SM);
    cudaFuncSetAttribute(imma_gemm<1,1>, cudaFuncAttributeMaxDynamicSharedMemorySize, SM);
    cudaFuncSetAttribute(imma_gemm<0,0>, cudaFuncAttributeMaxDynamicSharedMemorySize, SM);
    cudaFuncSetAttribute(imma_gemm<2,2>, cudaFuncAttributeMaxDynamicSharedMemorySize, SM);

    // 1) router (fp32)
    zero_cnt<<<1, 64>>>();
    router_gemm<<<BT/64, 256>>>(x, wr, pLog);
    router_topk<<<BT, 32>>>();
    scan_off<<<1, 32>>>();
    build_lists<<<NEXP, 256>>>();

    // 2) quantize x + shared weights; expert weight max prepass + repack-quant
    quant_rows<<<BT, 256>>>(x, Hh, pX_h, pX_l, psX);
    quant_rows<<<FFN, 256>>>(wsg, Hh, pSg_h, pSg_l, psSg);
    quant_rows<<<FFN, 256>>>(wsu, Hh, pSu_h, pSu_l, psSu);
    quant_rows<<<Hh, 256>>>(wsd, FFN, pSd_h, pSd_l, psSd);
    wmax_gu<<<dim3(NEXP/32, Ee), dim3(32,32)>>>(wgexp, psG);
    wmax_gu<<<dim3(NEXP/32, Ee), dim3(32,32)>>>(wuexp, psU);
    wmax_dn<<<dim3(NEXP/32, Hh), dim3(32,32)>>>(wdexp, psD);
    repackq_gu<<<dim3(Hh/32, NEXP/32, Ee), dim3(32,32)>>>(wgexp, psG, pWg_h, pWg_l);
    repackq_gu<<<dim3(Hh/32, NEXP/32, Ee), dim3(32,32)>>>(wuexp, psU, pWu_h, pWu_l);
    repackq_dn<<<dim3(Ee/32, NEXP/32, Hh), dim3(32,32)>>>(wdexp, psD, pWd_h, pWd_l);

    // 3) up GEMMs (fp32 act out)
    imma_gemm<1,0><<<dim3(BT/128, FFN/32), 256, SM>>>(
        pX_h, pX_l, psX, Hh,
        pSg_h, pSg_l, pSu_h, pSu_l, psSg, psSu, 0, 0,
        pShf, FFN, BT, Hh, 1);
    imma_gemm<1,1><<<dim3(BT/128, NEXP*(Ee/32)), 256, SM>>>(
        pX_h, pX_l, psX, Hh,
        pWg_h, pWg_l, pWu_h, pWu_l, psG, psU, Ee, (size_t)Ee*Hh,
        pActf, Ee, 0, Hh, Ee/32);

    // 4) quantize activations
    quant_rows<<<BT, 256>>>(pShf, FFN, pSh_h, pSh_l, psSh);
    quant_rows<<<TOT, 256>>>(pActf, Ee, pA_h, pA_l, psAct);

    // 5) down GEMMs
    imma_gemm<0,0><<<dim3(BT/128, Hh/64), 256, SM>>>(
        pSh_h, pSh_l, psSh, FFN,
        pSd_h, pSd_l, nullptr, nullptr, psSd, nullptr, 0, 0,
        out, Hh, BT, FFN, 1);
    imma_gemm<2,2><<<dim3(BT/128, NEXP*(Hh/64)), 256, SM>>>(
        pA_h, pA_l, psAct, Ee,
        pWd_h, pWd_l, nullptr, nullptr, psD, nullptr, Hh, (size_t)Hh*Ee,
        pDout, Hh, 0, Ee, Hh/64);

    // 6) combine routed + shared
    reduce_out<<<BT, 256>>>(out);
}

// round 10
// speedup vs baseline: 2.3894x; 2.3894x over previous
#include <cuda_runtime.h>
#include <cuda_fp16.h>
#include <cstdint>
#include <cstddef>

#define BT   2048
#define Hh   1280
#define Ee   896
#define NEXP 64
#define TOPK 6
#define FFN  1792
#define TOT  (BT*TOPK)

typedef __half fp16;

// ---------------- device scratch ----------------
// single-fp16 weights, per-expert row-major [n-row][k]
__device__ fp16 g_Wg[(size_t)NEXP*Ee*Hh];   // [exp][e][h]
__device__ fp16 g_Wu[(size_t)NEXP*Ee*Hh];
__device__ fp16 g_Wd[(size_t)NEXP*Hh*Ee];   // [exp][h][e]
__device__ fp16 g_Sg[(size_t)FFN*Hh];
__device__ fp16 g_Su[(size_t)FFN*Hh];
__device__ fp16 g_Sd[(size_t)Hh*FFN];
// activations: fp16 hi/lo (2-term split, ~22-bit effective)
__device__ fp16 g_xh[(size_t)BT*Hh],  g_xl[(size_t)BT*Hh];
__device__ fp16 g_shh[(size_t)BT*FFN], g_shl[(size_t)BT*FFN];
__device__ fp16 g_acth[(size_t)TOT*Ee], g_actl[(size_t)TOT*Ee];
__device__ float g_dout[(size_t)TOT*Hh];
// router
__device__ float g_logits[BT*NEXP];
__device__ int   g_topi[TOT];
__device__ float g_topw[TOT];
__device__ int   g_cnt[NEXP];
__device__ int   g_off[NEXP];
__device__ int   g_list[TOT];
__device__ float g_lw[TOT];
__device__ int   g_pos[TOT];

// ---------------- small kernels ----------------
__global__ void zero_cnt() { if (threadIdx.x < NEXP) g_cnt[threadIdx.x] = 0; }

__global__ void scan_off() {
    if (threadIdx.x == 0) {
        int a = 0;
        for (int n = 0; n < NEXP; n++) { g_off[n] = a; a += g_cnt[n]; }
    }
}

__global__ void router_topk() {
    int t = blockIdx.x;
    int lane = threadIdx.x;
    const float NEG = __int_as_float(0xff800000);
    float v0 = g_logits[t*NEXP + lane];
    float v1 = g_logits[t*NEXP + 32 + lane];
    int i0 = lane, i1 = lane + 32;
    float bv[TOPK]; int bi[TOPK];
    for (int k = 0; k < TOPK; k++) {
        float mv; int mi;
        if (v0 > v1 || (v0 == v1 && i0 < i1)) { mv = v0; mi = i0; } else { mv = v1; mi = i1; }
        for (int o = 16; o > 0; o >>= 1) {
            float ov = __shfl_xor_sync(0xffffffffu, mv, o);
            int   oi = __shfl_xor_sync(0xffffffffu, mi, o);
            if (ov > mv || (ov == mv && oi < mi)) { mv = ov; mi = oi; }
        }
        bv[k] = mv; bi[k] = mi;
        if (i0 == mi) v0 = NEG;
        if (i1 == mi) v1 = NEG;
    }
    float mx = bv[0];
    float s = 0.f, ev[TOPK];
    #pragma unroll
    for (int k = 0; k < TOPK; k++) { ev[k] = __expf(bv[k] - mx); s += ev[k]; }
    if (lane < TOPK) {
        g_topi[t*TOPK + lane] = bi[lane];
        g_topw[t*TOPK + lane] = ev[lane] / s;
        atomicAdd(&g_cnt[bi[lane]], 1);
    }
}

__global__ void build_lists() {
    int e = blockIdx.x;
    int tid = threadIdx.x;
    int lane = tid & 31, wid = tid >> 5;
    __shared__ int wcnt[8], wpre[8], stot;
    int base = g_off[e];
    int run = 0;
    for (int s0 = 0; s0 < TOT; s0 += 256) {
        int s = s0 + tid;
        bool p = (s < TOT) && (g_topi[s] == e);
        unsigned b = __ballot_sync(0xffffffffu, p);
        int wp = __popc(b & ((1u << lane) - 1u));
        if (lane == 0) wcnt[wid] = __popc(b);
        __syncthreads();
        if (tid == 0) {
            int a = 0;
            for (int w = 0; w < 8; w++) { wpre[w] = a; a += wcnt[w]; }
            stot = a;
        }
        __syncthreads();
        if (p) {
            int pos = base + run + wpre[wid] + wp;
            g_list[pos] = s / TOPK;
            g_lw[pos]   = g_topw[s];
            g_pos[s]    = pos;
        }
        run += stot;
        __syncthreads();
    }
}

// ---------------- split / convert / repack ----------------
__device__ __forceinline__ void split16(float v, fp16& h, fp16& l) {
    h = __float2half_rn(v);
    l = __float2half_rn(v - __half2float(h));
}

// x -> fp16 hi/lo
__global__ void splitx(const float* __restrict__ src, fp16* __restrict__ dh, fp16* __restrict__ dl, int n4) {
    int i = blockIdx.x * blockDim.x + threadIdx.x;
    if (i < n4) {
        float4 v = ((const float4*)src)[i];
        fp16 h[4], l[4];
        split16(v.x, h[0], l[0]); split16(v.y, h[1], l[1]);
        split16(v.z, h[2], l[2]); split16(v.w, h[3], l[3]);
        __half2 hh0, hh1, ll0, ll1;
        hh0 = __halves2half2(h[0], h[1]); hh1 = __halves2half2(h[2], h[3]);
        ll0 = __halves2half2(l[0], l[1]); ll1 = __halves2half2(l[2], l[3]);
        uint2 hp, lp;
        hp.x = *(uint32_t*)&hh0; hp.y = *(uint32_t*)&hh1;
        lp.x = *(uint32_t*)&ll0; lp.y = *(uint32_t*)&ll1;
        ((uint2*)dh)[i] = hp;
        ((uint2*)dl)[i] = lp;
    }
}

// fp32 -> fp16 elementwise (shared weights, layout preserved)
__global__ void cvt16(const float* __restrict__ src, fp16* __restrict__ dst, int n4) {
    int i = blockIdx.x * blockDim.x + threadIdx.x;
    if (i < n4) {
        float4 v = ((const float4*)src)[i];
        __half2 a = __halves2half2(__float2half_rn(v.x), __float2half_rn(v.y));
        __half2 b = __halves2half2(__float2half_rn(v.z), __float2half_rn(v.w));
        uint2 p; p.x = *(uint32_t*)&a; p.y = *(uint32_t*)&b;
        ((uint2*)dst)[i] = p;
    }
}

// gate/up: src [H][E][N] -> dst [exp][e][h] fp16
__global__ void repack_gu16(const float* __restrict__ src, fp16* __restrict__ dst) {
    __shared__ float s[32][33];
    int e = blockIdx.z;
    int h0 = blockIdx.x * 32, n0 = blockIdx.y * 32;
    int tx = threadIdx.x, ty = threadIdx.y;
    s[ty][tx] = src[(size_t)(h0+ty)*Ee*NEXP + (size_t)e*NEXP + (n0+tx)];
    __syncthreads();
    float v = s[tx][ty];  // (h = h0+tx, n = n0+ty)
    dst[(size_t)(n0+ty)*Ee*Hh + (size_t)e*Hh + (h0+tx)] = __float2half_rn(v);
}

// down: src [E][H][N] -> dst [exp][h][e] fp16
__global__ void repack_dn16(const float* __restrict__ src, fp16* __restrict__ dst) {
    __shared__ float s[32][33];
    int h = blockIdx.z;
    int e0 = blockIdx.x * 32, n0 = blockIdx.y * 32;
    int tx = threadIdx.x, ty = threadIdx.y;
    s[ty][tx] = src[(size_t)(e0+ty)*Hh*NEXP + (size_t)h*NEXP + (n0+tx)];
    __syncthreads();
    float v = s[tx][ty];  // (e = e0+tx, n = n0+ty)
    dst[(size_t)(n0+ty)*Hh*Ee + (size_t)h*Ee + (e0+tx)] = __float2half_rn(v);
}

// ---------------- fp32 router GEMM ----------------
__global__ __launch_bounds__(256) void router_gemm(
    const float* __restrict__ A, const float* __restrict__ B, float* __restrict__ C)
{
    const int m0 = blockIdx.x * 64;
    __shared__ __align__(16) float As[16][68];
    __shared__ __align__(16) float Bs[16][68];
    const int tid = threadIdx.x;
    const int tx = tid & 15, ty = tid >> 4;
    float acc[4][4];
    #pragma unroll
    for (int i = 0; i < 4; i++) for (int j = 0; j < 4; j++) acc[i][j] = 0.f;
    const int aCol = tid & 15, aRow0 = tid >> 4;
    for (int k0 = 0; k0 < Hh; k0 += 16) {
        #pragma unroll
        for (int i = 0; i < 4; i++)
            As[aCol][aRow0 + 16*i] = A[(size_t)(m0 + aRow0 + 16*i)*Hh + k0 + aCol];
        const int bK = tid & 15, bN0 = tid >> 4;
        #pragma unroll
        for (int i = 0; i < 4; i++)
            Bs[bK][bN0 + 16*i] = B[(size_t)(bN0 + 16*i)*Hh + k0 + bK];
        __syncthreads();
        #pragma unroll
        for (int kk = 0; kk < 16; kk++) {
            float4 a4 = *(const float4*)&As[kk][ty*4];
            float4 b4 = *(const float4*)&Bs[kk][tx*4];
            float av[4] = {a4.x,a4.y,a4.z,a4.w};
            float bv[4] = {b4.x,b4.y,b4.z,b4.w};
            #pragma unroll
            for (int i = 0; i < 4; i++) for (int j = 0; j < 4; j++) acc[i][j] += av[i]*bv[j];
        }
        __syncthreads();
    }
    #pragma unroll
    for (int i = 0; i < 4; i++) for (int j = 0; j < 4; j++)
        C[(size_t)(m0 + ty*4 + i)*NEXP + tx*4 + j] = acc[i][j];
}

// ---------------- MMA / cp.async helpers ----------------
__device__ __forceinline__ void ldsm_x4(uint32_t* r, const void* p) {
    uint32_t a = (uint32_t)__cvta_generic_to_shared(p);
    asm volatile("ldmatrix.sync.aligned.m8n8.x4.shared.b16 {%0,%1,%2,%3}, [%4];"
        : "=r"(r[0]), "=r"(r[1]), "=r"(r[2]), "=r"(r[3]) : "r"(a));
}
__device__ __forceinline__ void mma16816h(float* d, const uint32_t* a, const uint32_t* b) {
    asm volatile("mma.sync.aligned.m16n8k16.row.col.f32.f16.f16.f32 "
        "{%0,%1,%2,%3}, {%4,%5,%6,%7}, {%8,%9}, {%0,%1,%2,%3};"
        : "+f"(d[0]), "+f"(d[1]), "+f"(d[2]), "+f"(d[3])
        : "r"(a[0]), "r"(a[1]), "r"(a[2]), "r"(a[3]), "r"(b[0]), "r"(b[1]));
}
__device__ __forceinline__ void cp16(uint32_t dst, const void* src, bool pred) {
    int sz = pred ? 16 : 0;
    asm volatile("cp.async.ca.shared.global [%0], [%1], 16, %2;"
        :: "r"(dst), "l"(src), "r"(sz));
}
__device__ __forceinline__ void cp_commit() { asm volatile("cp.async.commit_group;" ::: "memory"); }
template<int N> __device__ __forceinline__ void cp_wait() { asm volatile("cp.async.wait_group %0;" :: "n"(N) : "memory"); }

// ---------------- 2-term split-fp16 MMA GEMM ----------------
// 128x64x32 tile, 8 warps, 3-stage cp.async ring, 2 CTAs/SM.
// A: fp16 hi/lo [rows][K] (activations, exact to ~22 bits). B: single fp16 per-expert [n][K].
// acc = Ah*B + Al*B  (2 MMAs per product)
// MODE: 0 fp32 store, 1 dual-B silu(g)*u split-store fp16 h/l, 2 weighted slot fp32 store
// AMODE: 0 plain rows, 1 gather via g_list (store rows = slots), 2 rows are slots
template<int MODE, int AMODE>
__global__ __launch_bounds__(256, 2) void mma2(
    const fp16* __restrict__ Ah, const fp16* __restrict__ Al, int lda,
    const fp16* __restrict__ B0, const fp16* __restrict__ B1,
    size_t bStride,
    float* __restrict__ C, fp16* __restrict__ Ch, fp16* __restrict__ Cl,
    int ldc, int M, int K, int ntiles)
{
    constexpr int NB = (MODE == 1) ? 2 : 1;
    constexpr int OFF_AL = 128*40;
    constexpr int OFF_B  = 2*128*40;
    constexpr int STG    = 2*128*40 + NB*64*40;   // elems per stage
    extern __shared__ __align__(16) fp16 sm[];

    const int mt = blockIdx.x;
    int e, nt;
    if (AMODE != 0) { e = blockIdx.y / ntiles; nt = blockIdx.y % ntiles; }
    else            { e = 0;                   nt = blockIdx.y; }
    const int m0 = mt * 128, n0 = nt * 64;
    int rows, base = 0;
    if (AMODE != 0) { rows = g_cnt[e]; base = g_off[e]; if (m0 >= rows) return; }
    else rows = M;

    const fp16* bsrc[NB];
    bsrc[0] = B0 + (size_t)e * bStride;
    if (MODE == 1) bsrc[1] = B1 + (size_t)e * bStride;

    const int tid = threadIdx.x, lane = tid & 31, wid = tid >> 5;
    const int wr = wid >> 1, wc = wid & 1;   // warp grid 4x2 (m x n), warp tile 32x32

    const uint32_t smbase = (uint32_t)__cvta_generic_to_shared(sm);

    // A cp.async: {hi,lo} x 128 rows x 4 chunks(16B) = 1024 -> 4/thread
    const fp16* aSrc[4];
    uint32_t aDst[4];
    bool aOk[4];
    #pragma unroll
    for (int i = 0; i < 4; i++) {
        int idx = i*256 + tid;
        int a = idx >> 9, rem = idx & 511;
        int r = rem >> 2, q = rem & 3;
        int gm = m0 + r;
        bool ok = gm < rows;
        int row = 0;
        if (ok) {
            if (AMODE == 1)      row = g_list[base + gm];
            else if (AMODE == 2) row = base + gm;
            else                 row = gm;
        }
        aSrc[i] = (a ? Al : Ah) + (size_t)row * lda + q*8;
        aOk[i]  = ok;
        aDst[i] = (uint32_t)(((a ? OFF_AL : 0) + r*40 + q*8) * 2);
    }
    // B cp.async: NB arrays x 64 rows x 4 chunks = NB*256 -> NB/thread
    const fp16* bSrc[NB];
    uint32_t bDst[NB];
    #pragma unroll
    for (int i = 0; i < NB; i++) {
        int idx = i*256 + tid;
        int arr = idx >> 8, rem = idx & 255;
        int r = rem >> 2, q = rem & 3;
        bSrc[i] = bsrc[arr] + (size_t)(n0 + r) * K + q*8;
        bDst[i] = (uint32_t)((OFF_B + arr*64*40 + r*40 + q*8) * 2);
    }

    float accg[2][4][4];
    float accu[MODE == 1 ? 2 : 1][4][4];
    #pragma unroll
    for (int fm = 0; fm < 2; fm++)
        #pragma unroll
        for (int fn = 0; fn < 4; fn++)
            #pragma unroll
            for (int q = 0; q < 4; q++) {
                accg[fm][fn][q] = 0.f;
                if (MODE == 1) accu[fm][fn][q] = 0.f;
            }

    const int nk = K / 32;

    // prologue: prefetch tiles 0,1 into stages 0,1
    #pragma unroll
    for (int s = 0; s < 2; s++) {
        const uint32_t sb = smbase + (uint32_t)(s * STG * 2);
        const int k0 = s * 32;
        #pragma unroll
        for (int i = 0; i < 4; i++) cp16(sb + aDst[i], aSrc[i] + k0, aOk[i]);
        #pragma unroll
        for (int i = 0; i < NB; i++) cp16(sb + bDst[i], bSrc[i] + k0, true);
        cp_commit();
    }

    for (int kt = 0; kt < nk; kt++) {
        const int st = kt % 3;
        if (kt + 2 < nk) {
            const int k0 = (kt + 2) * 32;
            const uint32_t sb = smbase + (uint32_t)(((kt + 2) % 3) * STG * 2);
            #pragma unroll
            for (int i = 0; i < 4; i++) cp16(sb + aDst[i], aSrc[i] + k0, aOk[i]);
            #pragma unroll
            for (int i = 0; i < NB; i++) cp16(sb + bDst[i], bSrc[i] + k0, true);
            cp_commit();
            cp_wait<2>();
        } else if (kt + 1 < nk) {
            cp_wait<1>();
        } else {
            cp_wait<0>();
        }
        __syncthreads();

        fp16* pAh = sm + st * STG;
        fp16* pAl = pAh + OFF_AL;
        fp16* pB  = pAh + OFF_B;

        #pragma unroll
        for (int kk = 0; kk < 32; kk += 16) {
            // A fragments
            uint32_t ah[2][4], al[2][4];
            #pragma unroll
            for (int fm = 0; fm < 2; fm++) {
                int arow = wr*32 + fm*16 + (lane & 15);
                int acol = kk + (lane >> 4) * 8;
                ldsm_x4(ah[fm], pAh + arow*40 + acol);
                ldsm_x4(al[fm], pAl + arow*40 + acol);
            }
            // B fragments via x4 (two fn blocks per load)
            uint32_t bfr[NB][4][2];
            #pragma unroll
            for (int fp = 0; fp < 2; fp++) {
                int brow = wc*32 + fp*16 + ((lane >> 4) << 3) + (lane & 7);
                int bcol = kk + ((lane >> 3) & 1) * 8;
                #pragma unroll
                for (int arr = 0; arr < NB; arr++) {
                    uint32_t r4[4];
                    ldsm_x4(r4, pB + arr*64*40 + brow*40 + bcol);
                    bfr[arr][2*fp+0][0] = r4[0]; bfr[arr][2*fp+0][1] = r4[1];
                    bfr[arr][2*fp+1][0] = r4[2]; bfr[arr][2*fp+1][1] = r4[3];
                }
            }
            // MMA: acc += Ah*B + Al*B
            #pragma unroll
            for (int fn = 0; fn < 4; fn++) {
                #pragma unroll
                for (int fm = 0; fm < 2; fm++) {
                    mma16816h(accg[fm][fn], ah[fm], bfr[0][fn]);
                    mma16816h(accg[fm][fn], al[fm], bfr[0][fn]);
                    if (MODE == 1) {
                        mma16816h(accu[fm][fn], ah[fm], bfr[1][fn]);
                        mma16816h(accu[fm][fn], al[fm], bfr[1][fn]);
                    }
                }
            }
        }
        __syncthreads();
    }

    // epilogue
    #pragma unroll
    for (int fm = 0; fm < 2; fm++) {
        int rbase = m0 + wr*32 + fm*16 + (lane >> 2);
        #pragma unroll
        for (int half = 0; half < 2; half++) {
            int gm = rbase + half*8;
            if (AMODE != 0 && gm >= rows) continue;
            float w = 0.f;
            if (MODE == 2) w = g_lw[base + gm];
            #pragma unroll
            for (int fn = 0; fn < 4; fn++) {
                int col = n0 + wc*32 + fn*8 + (lane & 3)*2;
                float c0 = accg[fm][fn][half*2+0];
                float c1 = accg[fm][fn][half*2+1];
                if (MODE == 0) {
                    *(float2*)&C[(size_t)gm * ldc + col] = make_float2(c0, c1);
                } else if (MODE == 1) {
                    float u0 = accu[fm][fn][half*2+0];
                    float u1 = accu[fm][fn][half*2+1];
                    float s0 = c0 / (1.f + __expf(-c0)) * u0;
                    float s1 = c1 / (1.f + __expf(-c1)) * u1;
                    int rc = (AMODE != 0) ? (base + gm) : gm;
                    fp16 h0,l0,h1,l1;
                    split16(s0,h0,l0); split16(s1,h1,l1);
                    __half2 hh = __halves2half2(h0, h1);
                    __half2 ll = __halves2half2(l0, l1);
                    *(__half2*)&Ch[(size_t)rc * ldc + col] = hh;
                    *(__half2*)&Cl[(size_t)rc * ldc + col] = ll;
                } else { // MODE == 2
                    int rc = base + gm;
                    *(float2*)&C[(size_t)rc * ldc + col] = make_float2(c0 * w, c1 * w);
                }
            }
        }
    }
}

// ---------------- final gather-reduce ----------------
__global__ void reduce_out(float* __restrict__ out) {
    int t = blockIdx.x;
    int p[TOPK];
    #pragma unroll
    for (int k = 0; k < TOPK; k++) p[k] = g_pos[t*TOPK + k];
    float4* o4 = (float4*)(out + (size_t)t * Hh);
    for (int c = threadIdx.x; c < Hh/4; c += blockDim.x) {
        float4 v = o4[c];
        #pragma unroll
        for (int k = 0; k < TOPK; k++) {
            float4 d = ((const float4*)(g_dout + (size_t)p[k] * Hh))[c];
            v.x += d.x; v.y += d.y; v.z += d.z; v.w += d.w;
        }
        o4[c] = v;
    }
}

// ---------------- launch ----------------
extern "C" void kernel_launch(void* const* d_in, const int* in_sizes, int n_in,
                              void* d_out, int out_size) {
    const float* x      = (const float*)d_in[0];
    const float* wr     = (const float*)d_in[1];
    const float* wgexp  = (const float*)d_in[2];
    const float* wuexp  = (const float*)d_in[3];
    const float* wdexp  = (const float*)d_in[4];
    const float* wsg    = (const float*)d_in[5];
    const float* wsu    = (const float*)d_in[6];
    const float* wsd    = (const float*)d_in[7];
    float* out = (float*)d_out;

    float *pLog, *pDout;
    fp16 *pWg,*pWu,*pWd,*pSg,*pSu,*pSd;
    fp16 *pXh,*pXl,*pShh,*pShl,*pAh,*pAl;
    cudaGetSymbolAddress((void**)&pLog, g_logits);
    cudaGetSymbolAddress((void**)&pDout, g_dout);
    cudaGetSymbolAddress((void**)&pWg, g_Wg);
    cudaGetSymbolAddress((void**)&pWu, g_Wu);
    cudaGetSymbolAddress((void**)&pWd, g_Wd);
    cudaGetSymbolAddress((void**)&pSg, g_Sg);
    cudaGetSymbolAddress((void**)&pSu, g_Su);
    cudaGetSymbolAddress((void**)&pSd, g_Sd);
    cudaGetSymbolAddress((void**)&pXh, g_xh);   cudaGetSymbolAddress((void**)&pXl, g_xl);
    cudaGetSymbolAddress((void**)&pShh, g_shh); cudaGetSymbolAddress((void**)&pShl, g_shl);
    cudaGetSymbolAddress((void**)&pAh, g_acth); cudaGetSymbolAddress((void**)&pAl, g_actl);

    const int SM1 = (2*128*40 + 2*64*40) * 2 * 3;  // MODE=1: 92160 B
    const int SM0 = (2*128*40 + 1*64*40) * 2 * 3;  // MODE=0/2: 76800 B
    cudaFuncSetAttribute(mma2<1,0>, cudaFuncAttributeMaxDynamicSharedMemorySize, SM1);
    cudaFuncSetAttribute(mma2<1,1>, cudaFuncAttributeMaxDynamicSharedMemorySize, SM1);
    cudaFuncSetAttribute(mma2<0,0>, cudaFuncAttributeMaxDynamicSharedMemorySize, SM0);
    cudaFuncSetAttribute(mma2<2,2>, cudaFuncAttributeMaxDynamicSharedMemorySize, SM0);

    // 1) router (fp32)
    zero_cnt<<<1, 64>>>();
    router_gemm<<<BT/64, 256>>>(x, wr, pLog);
    router_topk<<<BT, 32>>>();
    scan_off<<<1, 32>>>();
    build_lists<<<NEXP, 256>>>();

    // 2) split x; convert + repack weights (single fp16)
    splitx<<<(BT*Hh/4 + 255)/256, 256>>>(x, pXh, pXl, BT*Hh/4);
    cvt16<<<(FFN*Hh/4 + 255)/256, 256>>>(wsg, pSg, FFN*Hh/4);
    cvt16<<<(FFN*Hh/4 + 255)/256, 256>>>(wsu, pSu, FFN*Hh/4);
    cvt16<<<(Hh*FFN/4 + 255)/256, 256>>>(wsd, pSd, Hh*FFN/4);
    repack_gu16<<<dim3(Hh/32, NEXP/32, Ee), dim3(32,32)>>>(wgexp, pWg);
    repack_gu16<<<dim3(Hh/32, NEXP/32, Ee), dim3(32,32)>>>(wuexp, pWu);
    repack_dn16<<<dim3(Ee/32, NEXP/32, Hh), dim3(32,32)>>>(wdexp, pWd);

    // 3) up GEMMs (silu(g)*u, split-store fp16 hi/lo)
    mma2<1,0><<<dim3(BT/128, FFN/64), 256, SM1>>>(
        pXh, pXl, Hh, pSg, pSu, 0,
        nullptr, pShh, pShl, FFN, BT, Hh, 1);
    mma2<1,1><<<dim3(BT/128, NEXP*(Ee/64)), 256, SM1>>>(
        pXh, pXl, Hh, pWg, pWu, (size_t)Ee*Hh,
        nullptr, pAh, pAl, Ee, 0, Hh, Ee/64);

    // 4) down GEMMs
    mma2<0,0><<<dim3(BT/128, Hh/64), 256, SM0>>>(
        pShh, pShl, FFN, pSd, nullptr, 0,
        out, nullptr, nullptr, Hh, BT, FFN, 1);
    mma2<2,2><<<dim3(BT/128, NEXP*(Hh/64)), 256, SM0>>>(
        pAh, pAl, Ee, pWd, nullptr, (size_t)Hh*Ee,
        pDout, nullptr, nullptr, Hh, 0, Ee, Hh/64);

    // 5) combine routed + shared
    reduce_out<<<BT, 256>>>(out);
}

// round 11
// speedup vs baseline: 2.9030x; 1.2150x over previous
#include <cuda_runtime.h>
#include <cuda_fp16.h>
#include <cstdint>
#include <cstddef>

#define BT   2048
#define Hh   1280
#define Ee   896
#define NEXP 64
#define TOPK 6
#define FFN  1792
#define TOT  (BT*TOPK)

typedef __half fp16;

// ---------------- device scratch ----------------
__device__ fp16 g_Wg[(size_t)NEXP*Ee*Hh];   // [exp][e][h]
__device__ fp16 g_Wu[(size_t)NEXP*Ee*Hh];
__device__ fp16 g_Wd[(size_t)NEXP*Hh*Ee];   // [exp][h][e]
__device__ fp16 g_Sg[(size_t)FFN*Hh];
__device__ fp16 g_Su[(size_t)FFN*Hh];
__device__ fp16 g_Sd[(size_t)Hh*FFN];
// single-fp16 activations
__device__ fp16 g_x16[(size_t)BT*Hh];
__device__ fp16 g_sh16[(size_t)BT*FFN];
__device__ fp16 g_act16[(size_t)TOT*Ee];
__device__ float g_dout[(size_t)TOT*Hh];
// router
__device__ float g_logits[BT*NEXP];
__device__ int   g_topi[TOT];
__device__ float g_topw[TOT];
__device__ int   g_cnt[NEXP];
__device__ int   g_off[NEXP];
__device__ int   g_list[TOT];
__device__ float g_lw[TOT];
__device__ int   g_pos[TOT];

// ---------------- small kernels ----------------
__global__ void zero_cnt() { if (threadIdx.x < NEXP) g_cnt[threadIdx.x] = 0; }

__global__ void scan_off() {
    if (threadIdx.x == 0) {
        int a = 0;
        for (int n = 0; n < NEXP; n++) { g_off[n] = a; a += g_cnt[n]; }
    }
}

__global__ void router_topk() {
    int t = blockIdx.x;
    int lane = threadIdx.x;
    const float NEG = __int_as_float(0xff800000);
    float v0 = g_logits[t*NEXP + lane];
    float v1 = g_logits[t*NEXP + 32 + lane];
    int i0 = lane, i1 = lane + 32;
    float bv[TOPK]; int bi[TOPK];
    for (int k = 0; k < TOPK; k++) {
        float mv; int mi;
        if (v0 > v1 || (v0 == v1 && i0 < i1)) { mv = v0; mi = i0; } else { mv = v1; mi = i1; }
        for (int o = 16; o > 0; o >>= 1) {
            float ov = __shfl_xor_sync(0xffffffffu, mv, o);
            int   oi = __shfl_xor_sync(0xffffffffu, mi, o);
            if (ov > mv || (ov == mv && oi < mi)) { mv = ov; mi = oi; }
        }
        bv[k] = mv; bi[k] = mi;
        if (i0 == mi) v0 = NEG;
        if (i1 == mi) v1 = NEG;
    }
    float mx = bv[0];
    float s = 0.f, ev[TOPK];
    #pragma unroll
    for (int k = 0; k < TOPK; k++) { ev[k] = __expf(bv[k] - mx); s += ev[k]; }
    if (lane < TOPK) {
        g_topi[t*TOPK + lane] = bi[lane];
        g_topw[t*TOPK + lane] = ev[lane] / s;
        atomicAdd(&g_cnt[bi[lane]], 1);
    }
}

__global__ void build_lists() {
    int e = blockIdx.x;
    int tid = threadIdx.x;
    int lane = tid & 31, wid = tid >> 5;
    __shared__ int wcnt[8], wpre[8], stot;
    int base = g_off[e];
    int run = 0;
    for (int s0 = 0; s0 < TOT; s0 += 256) {
        int s = s0 + tid;
        bool p = (s < TOT) && (g_topi[s] == e);
        unsigned b = __ballot_sync(0xffffffffu, p);
        int wp = __popc(b & ((1u << lane) - 1u));
        if (lane == 0) wcnt[wid] = __popc(b);
        __syncthreads();
        if (tid == 0) {
            int a = 0;
            for (int w = 0; w < 8; w++) { wpre[w] = a; a += wcnt[w]; }
            stot = a;
        }
        __syncthreads();
        if (p) {
            int pos = base + run + wpre[wid] + wp;
            g_list[pos] = s / TOPK;
            g_lw[pos]   = g_topw[s];
            g_pos[s]    = pos;
        }
        run += stot;
        __syncthreads();
    }
}

// ---------------- convert / repack ----------------
// fp32 -> fp16 elementwise (layout preserved)
__global__ void cvt16(const float* __restrict__ src, fp16* __restrict__ dst, int n4) {
    int i = blockIdx.x * blockDim.x + threadIdx.x;
    if (i < n4) {
        float4 v = ((const float4*)src)[i];
        __half2 a = __halves2half2(__float2half_rn(v.x), __float2half_rn(v.y));
        __half2 b = __halves2half2(__float2half_rn(v.z), __float2half_rn(v.w));
        uint2 p; p.x = *(uint32_t*)&a; p.y = *(uint32_t*)&b;
        ((uint2*)dst)[i] = p;
    }
}

// gate/up: src [H][E][N] -> dst [exp][e][h] fp16
__global__ void repack_gu16(const float* __restrict__ src, fp16* __restrict__ dst) {
    __shared__ float s[32][33];
    int e = blockIdx.z;
    int h0 = blockIdx.x * 32, n0 = blockIdx.y * 32;
    int tx = threadIdx.x, ty = threadIdx.y;
    s[ty][tx] = src[(size_t)(h0+ty)*Ee*NEXP + (size_t)e*NEXP + (n0+tx)];
    __syncthreads();
    float v = s[tx][ty];  // (h = h0+tx, n = n0+ty)
    dst[(size_t)(n0+ty)*Ee*Hh + (size_t)e*Hh + (h0+tx)] = __float2half_rn(v);
}

// down: src [E][H][N] -> dst [exp][h][e] fp16
__global__ void repack_dn16(const float* __restrict__ src, fp16* __restrict__ dst) {
    __shared__ float s[32][33];
    int h = blockIdx.z;
    int e0 = blockIdx.x * 32, n0 = blockIdx.y * 32;
    int tx = threadIdx.x, ty = threadIdx.y;
    s[ty][tx] = src[(size_t)(e0+ty)*Hh*NEXP + (size_t)h*NEXP + (n0+tx)];
    __syncthreads();
    float v = s[tx][ty];  // (e = e0+tx, n = n0+ty)
    dst[(size_t)(n0+ty)*Hh*Ee + (size_t)h*Ee + (e0+tx)] = __float2half_rn(v);
}

// ---------------- fp32 router GEMM ----------------
__global__ __launch_bounds__(256) void router_gemm(
    const float* __restrict__ A, const float* __restrict__ B, float* __restrict__ C)
{
    const int m0 = blockIdx.x * 64;
    __shared__ __align__(16) float As[16][68];
    __shared__ __align__(16) float Bs[16][68];
    const int tid = threadIdx.x;
    const int tx = tid & 15, ty = tid >> 4;
    float acc[4][4];
    #pragma unroll
    for (int i = 0; i < 4; i++) for (int j = 0; j < 4; j++) acc[i][j] = 0.f;
    const int aCol = tid & 15, aRow0 = tid >> 4;
    for (int k0 = 0; k0 < Hh; k0 += 16) {
        #pragma unroll
        for (int i = 0; i < 4; i++)
            As[aCol][aRow0 + 16*i] = A[(size_t)(m0 + aRow0 + 16*i)*Hh + k0 + aCol];
        const int bK = tid & 15, bN0 = tid >> 4;
        #pragma unroll
        for (int i = 0; i < 4; i++)
            Bs[bK][bN0 + 16*i] = B[(size_t)(bN0 + 16*i)*Hh + k0 + bK];
        __syncthreads();
        #pragma unroll
        for (int kk = 0; kk < 16; kk++) {
            float4 a4 = *(const float4*)&As[kk][ty*4];
            float4 b4 = *(const float4*)&Bs[kk][tx*4];
            float av[4] = {a4.x,a4.y,a4.z,a4.w};
            float bv[4] = {b4.x,b4.y,b4.z,b4.w};
            #pragma unroll
            for (int i = 0; i < 4; i++) for (int j = 0; j < 4; j++) acc[i][j] += av[i]*bv[j];
        }
        __syncthreads();
    }
    #pragma unroll
    for (int i = 0; i < 4; i++) for (int j = 0; j < 4; j++)
        C[(size_t)(m0 + ty*4 + i)*NEXP + tx*4 + j] = acc[i][j];
}

// ---------------- MMA / cp.async helpers ----------------
__device__ __forceinline__ void ldsm_x4(uint32_t* r, const void* p) {
    uint32_t a = (uint32_t)__cvta_generic_to_shared(p);
    asm volatile("ldmatrix.sync.aligned.m8n8.x4.shared.b16 {%0,%1,%2,%3}, [%4];"
        : "=r"(r[0]), "=r"(r[1]), "=r"(r[2]), "=r"(r[3]) : "r"(a));
}
__device__ __forceinline__ void mma16816h(float* d, const uint32_t* a, const uint32_t* b) {
    asm volatile("mma.sync.aligned.m16n8k16.row.col.f32.f16.f16.f32 "
        "{%0,%1,%2,%3}, {%4,%5,%6,%7}, {%8,%9}, {%0,%1,%2,%3};"
        : "+f"(d[0]), "+f"(d[1]), "+f"(d[2]), "+f"(d[3])
        : "r"(a[0]), "r"(a[1]), "r"(a[2]), "r"(a[3]), "r"(b[0]), "r"(b[1]));
}
__device__ __forceinline__ void cp16(uint32_t dst, const void* src, bool pred) {
    int sz = pred ? 16 : 0;
    asm volatile("cp.async.ca.shared.global [%0], [%1], 16, %2;"
        :: "r"(dst), "l"(src), "r"(sz));
}
__device__ __forceinline__ void cp_commit() { asm volatile("cp.async.commit_group;" ::: "memory"); }
template<int N> __device__ __forceinline__ void cp_wait() { asm volatile("cp.async.wait_group %0;" :: "n"(N) : "memory"); }

// ---------------- single-fp16 MMA GEMM ----------------
// 128x64x32 tile, 8 warps, 3-stage cp.async ring, 2 CTAs/SM.
// A: fp16 [rows][K]. B: fp16 per-expert [n][K]. 1 MMA per product.
// MODE: 0 fp32 store, 1 dual-B silu(g)*u -> fp16 store, 2 weighted slot fp32 store
// AMODE: 0 plain rows, 1 gather via g_list (store rows = slots), 2 rows are slots
template<int MODE, int AMODE>
__global__ __launch_bounds__(256, 2) void mma2(
    const fp16* __restrict__ A, int lda,
    const fp16* __restrict__ B0, const fp16* __restrict__ B1,
    size_t bStride,
    float* __restrict__ C, fp16* __restrict__ Cq,
    int ldc, int M, int K, int ntiles)
{
    constexpr int NB = (MODE == 1) ? 2 : 1;
    constexpr int OFF_B = 128*40;
    constexpr int STG   = 128*40 + NB*64*40;   // elems per stage
    extern __shared__ __align__(16) fp16 sm[];

    const int mt = blockIdx.x;
    int e, nt;
    if (AMODE != 0) { e = blockIdx.y / ntiles; nt = blockIdx.y % ntiles; }
    else            { e = 0;                   nt = blockIdx.y; }
    const int m0 = mt * 128, n0 = nt * 64;
    int rows, base = 0;
    if (AMODE != 0) { rows = g_cnt[e]; base = g_off[e]; if (m0 >= rows) return; }
    else rows = M;

    const fp16* bsrc[NB];
    bsrc[0] = B0 + (size_t)e * bStride;
    if (MODE == 1) bsrc[1] = B1 + (size_t)e * bStride;

    const int tid = threadIdx.x, lane = tid & 31, wid = tid >> 5;
    const int wr = wid >> 1, wc = wid & 1;   // warp grid 4x2 (m x n), warp tile 32x32

    const uint32_t smbase = (uint32_t)__cvta_generic_to_shared(sm);

    // A cp.async: 128 rows x 4 chunks(16B) = 512 -> 2/thread
    const fp16* aSrc[2];
    uint32_t aDst[2];
    bool aOk[2];
    #pragma unroll
    for (int i = 0; i < 2; i++) {
        int idx = i*256 + tid;
        int r = idx >> 2, q = idx & 3;
        int gm = m0 + r;
        bool ok = gm < rows;
        int row = 0;
        if (ok) {
            if (AMODE == 1)      row = g_list[base + gm];
            else if (AMODE == 2) row = base + gm;
            else                 row = gm;
        }
        aSrc[i] = A + (size_t)row * lda + q*8;
        aOk[i]  = ok;
        aDst[i] = (uint32_t)((r*40 + q*8) * 2);
    }
    // B cp.async: NB arrays x 64 rows x 4 chunks = NB*256 -> NB/thread
    const fp16* bSrc[NB];
    uint32_t bDst[NB];
    #pragma unroll
    for (int i = 0; i < NB; i++) {
        int idx = i*256 + tid;
        int arr = idx >> 8, rem = idx & 255;
        int r = rem >> 2, q = rem & 3;
        bSrc[i] = bsrc[arr] + (size_t)(n0 + r) * K + q*8;
        bDst[i] = (uint32_t)((OFF_B + arr*64*40 + r*40 + q*8) * 2);
    }

    float accg[2][4][4];
    float accu[MODE == 1 ? 2 : 1][4][4];
    #pragma unroll
    for (int fm = 0; fm < 2; fm++)
        #pragma unroll
        for (int fn = 0; fn < 4; fn++)
            #pragma unroll
            for (int q = 0; q < 4; q++) {
                accg[fm][fn][q] = 0.f;
                if (MODE == 1) accu[fm][fn][q] = 0.f;
            }

    const int nk = K / 32;

    // prologue: prefetch tiles 0,1 into stages 0,1
    #pragma unroll
    for (int s = 0; s < 2; s++) {
        const uint32_t sb = smbase + (uint32_t)(s * STG * 2);
        const int k0 = s * 32;
        #pragma unroll
        for (int i = 0; i < 2; i++) cp16(sb + aDst[i], aSrc[i] + k0, aOk[i]);
        #pragma unroll
        for (int i = 0; i < NB; i++) cp16(sb + bDst[i], bSrc[i] + k0, true);
        cp_commit();
    }

    for (int kt = 0; kt < nk; kt++) {
        const int st = kt % 3;
        if (kt + 2 < nk) {
            const int k0 = (kt + 2) * 32;
            const uint32_t sb = smbase + (uint32_t)(((kt + 2) % 3) * STG * 2);
            #pragma unroll
            for (int i = 0; i < 2; i++) cp16(sb + aDst[i], aSrc[i] + k0, aOk[i]);
            #pragma unroll
            for (int i = 0; i < NB; i++) cp16(sb + bDst[i], bSrc[i] + k0, true);
            cp_commit();
            cp_wait<2>();
        } else if (kt + 1 < nk) {
            cp_wait<1>();
        } else {
            cp_wait<0>();
        }
        __syncthreads();

        fp16* pA = sm + st * STG;
        fp16* pB = pA + OFF_B;

        #pragma unroll
        for (int kk = 0; kk < 32; kk += 16) {
            // A fragments
            uint32_t fa[2][4];
            #pragma unroll
            for (int fm = 0; fm < 2; fm++) {
                int arow = wr*32 + fm*16 + (lane & 15);
                int acol = kk + (lane >> 4) * 8;
                ldsm_x4(fa[fm], pA + arow*40 + acol);
            }
            // B fragments via x4 (two fn blocks per load)
            uint32_t bfr[NB][4][2];
            #pragma unroll
            for (int fp = 0; fp < 2; fp++) {
                int brow = wc*32 + fp*16 + ((lane >> 4) << 3) + (lane & 7);
                int bcol = kk + ((lane >> 3) & 1) * 8;
                #pragma unroll
                for (int arr = 0; arr < NB; arr++) {
                    uint32_t r4[4];
                    ldsm_x4(r4, pB + arr*64*40 + brow*40 + bcol);
                    bfr[arr][2*fp+0][0] = r4[0]; bfr[arr][2*fp+0][1] = r4[1];
                    bfr[arr][2*fp+1][0] = r4[2]; bfr[arr][2*fp+1][1] = r4[3];
                }
            }
            // MMA: 1 per product
            #pragma unroll
            for (int fn = 0; fn < 4; fn++) {
                #pragma unroll
                for (int fm = 0; fm < 2; fm++) {
                    mma16816h(accg[fm][fn], fa[fm], bfr[0][fn]);
                    if (MODE == 1) mma16816h(accu[fm][fn], fa[fm], bfr[1][fn]);
                }
            }
        }
        __syncthreads();
    }

    // epilogue
    #pragma unroll
    for (int fm = 0; fm < 2; fm++) {
        int rbase = m0 + wr*32 + fm*16 + (lane >> 2);
        #pragma unroll
        for (int half = 0; half < 2; half++) {
            int gm = rbase + half*8;
            if (AMODE != 0 && gm >= rows) continue;
            float w = 0.f;
            if (MODE == 2) w = g_lw[base + gm];
            #pragma unroll
            for (int fn = 0; fn < 4; fn++) {
                int col = n0 + wc*32 + fn*8 + (lane & 3)*2;
                float c0 = accg[fm][fn][half*2+0];
                float c1 = accg[fm][fn][half*2+1];
                if (MODE == 0) {
                    *(float2*)&C[(size_t)gm * ldc + col] = make_float2(c0, c1);
                } else if (MODE == 1) {
                    float u0 = accu[fm][fn][half*2+0];
                    float u1 = accu[fm][fn][half*2+1];
                    float s0 = c0 / (1.f + __expf(-c0)) * u0;
                    float s1 = c1 / (1.f + __expf(-c1)) * u1;
                    int rc = (AMODE != 0) ? (base + gm) : gm;
                    __half2 hh = __halves2half2(__float2half_rn(s0), __float2half_rn(s1));
                    *(__half2*)&Cq[(size_t)rc * ldc + col] = hh;
                } else { // MODE == 2
                    int rc = base + gm;
                    *(float2*)&C[(size_t)rc * ldc + col] = make_float2(c0 * w, c1 * w);
                }
            }
        }
    }
}

// ---------------- final gather-reduce ----------------
__global__ void reduce_out(float* __restrict__ out) {
    int t = blockIdx.x;
    int p[TOPK];
    #pragma unroll
    for (int k = 0; k < TOPK; k++) p[k] = g_pos[t*TOPK + k];
    float4* o4 = (float4*)(out + (size_t)t * Hh);
    for (int c = threadIdx.x; c < Hh/4; c += blockDim.x) {
        float4 v = o4[c];
        #pragma unroll
        for (int k = 0; k < TOPK; k++) {
            float4 d = ((const float4*)(g_dout + (size_t)p[k] * Hh))[c];
            v.x += d.x; v.y += d.y; v.z += d.z; v.w += d.w;
        }
        o4[c] = v;
    }
}

// ---------------- launch ----------------
extern "C" void kernel_launch(void* const* d_in, const int* in_sizes, int n_in,
                              void* d_out, int out_size) {
    const float* x      = (const float*)d_in[0];
    const float* wr     = (const float*)d_in[1];
    const float* wgexp  = (const float*)d_in[2];
    const float* wuexp  = (const float*)d_in[3];
    const float* wdexp  = (const float*)d_in[4];
    const float* wsg    = (const float*)d_in[5];
    const float* wsu    = (const float*)d_in[6];
    const float* wsd    = (const float*)d_in[7];
    float* out = (float*)d_out;

    float *pLog, *pDout;
    fp16 *pWg,*pWu,*pWd,*pSg,*pSu,*pSd;
    fp16 *pX16,*pSh16,*pAct16;
    cudaGetSymbolAddress((void**)&pLog, g_logits);
    cudaGetSymbolAddress((void**)&pDout, g_dout);
    cudaGetSymbolAddress((void**)&pWg, g_Wg);
    cudaGetSymbolAddress((void**)&pWu, g_Wu);
    cudaGetSymbolAddress((void**)&pWd, g_Wd);
    cudaGetSymbolAddress((void**)&pSg, g_Sg);
    cudaGetSymbolAddress((void**)&pSu, g_Su);
    cudaGetSymbolAddress((void**)&pSd, g_Sd);
    cudaGetSymbolAddress((void**)&pX16, g_x16);
    cudaGetSymbolAddress((void**)&pSh16, g_sh16);
    cudaGetSymbolAddress((void**)&pAct16, g_act16);

    const int SM1 = (128*40 + 2*64*40) * 2 * 3;  // MODE=1: 61440 B
    const int SM0 = (128*40 + 1*64*40) * 2 * 3;  // MODE=0/2: 46080 B
    cudaFuncSetAttribute(mma2<1,0>, cudaFuncAttributeMaxDynamicSharedMemorySize, SM1);
    cudaFuncSetAttribute(mma2<1,1>, cudaFuncAttributeMaxDynamicSharedMemorySize, SM1);
    cudaFuncSetAttribute(mma2<0,0>, cudaFuncAttributeMaxDynamicSharedMemorySize, SM0);
    cudaFuncSetAttribute(mma2<2,2>, cudaFuncAttributeMaxDynamicSharedMemorySize, SM0);

    // 1) router (fp32 — top-k ordering must match reference)
    zero_cnt<<<1, 64>>>();
    router_gemm<<<BT/64, 256>>>(x, wr, pLog);
    router_topk<<<BT, 32>>>();
    scan_off<<<1, 32>>>();
    build_lists<<<NEXP, 256>>>();

    // 2) convert x + weights to fp16 (repack expert weights)
    cvt16<<<(BT*Hh/4 + 255)/256, 256>>>(x, pX16, BT*Hh/4);
    cvt16<<<(FFN*Hh/4 + 255)/256, 256>>>(wsg, pSg, FFN*Hh/4);
    cvt16<<<(FFN*Hh/4 + 255)/256, 256>>>(wsu, pSu, FFN*Hh/4);
    cvt16<<<(Hh*FFN/4 + 255)/256, 256>>>(wsd, pSd, Hh*FFN/4);
    repack_gu16<<<dim3(Hh/32, NEXP/32, Ee), dim3(32,32)>>>(wgexp, pWg);
    repack_gu16<<<dim3(Hh/32, NEXP/32, Ee), dim3(32,32)>>>(wuexp, pWu);
    repack_dn16<<<dim3(Ee/32, NEXP/32, Hh), dim3(32,32)>>>(wdexp, pWd);

    // 3) up GEMMs (silu(g)*u -> fp16)
    mma2<1,0><<<dim3(BT/128, FFN/64), 256, SM1>>>(
        pX16, Hh, pSg, pSu, 0,
        nullptr, pSh16, FFN, BT, Hh, 1);
    mma2<1,1><<<dim3(BT/128, NEXP*(Ee/64)), 256, SM1>>>(
        pX16, Hh, pWg, pWu, (size_t)Ee*Hh,
        nullptr, pAct16, Ee, 0, Hh, Ee/64);

    // 4) down GEMMs
    mma2<0,0><<<dim3(BT/128, Hh/64), 256, SM0>>>(
        pSh16, FFN, pSd, nullptr, 0,
        out, nullptr, Hh, BT, FFN, 1);
    mma2<2,2><<<dim3(BT/128, NEXP*(Hh/64)), 256, SM0>>>(
        pAct16, Ee, pWd, nullptr, (size_t)Hh*Ee,
        pDout, nullptr, Hh, 0, Ee, Hh/64);

    // 5) combine routed + shared
    reduce_out<<<BT, 256>>>(out);
}